// round 1
// baseline (speedup 1.0000x reference)
#include <cuda_runtime.h>
#include <cstdint>

// nODE_7284264534323: 50 Euler steps of x <- x + DT*(x*gamma + tanh(x @ W^T + b))
// M=32768, N=K=512. Fused GEMM+epilogue per step, 50 launches (graph-capturable),
// ping-pong through __device__ scratch. GEMM in tf32 via mma.sync.m16n8k8.

constexpr int Mtot = 32768;
constexpr int Ntot = 512;
constexpr int Ktot = 512;
constexpr int BM = 128;
constexpr int BN = 64;
constexpr int BK = 32;
constexpr int PAD = 4;            // smem padding (words): bank = (4*g + tg) -> conflict-free
constexpr int NSTEPS = 50;
constexpr float DTF = 1.0f / 50.0f;

// Scratch ping-pong buffers (allocation-free rule: __device__ globals)
__device__ float g_bufA[(size_t)Mtot * Ntot];
__device__ float g_bufB[(size_t)Mtot * Ntot];

__device__ __forceinline__ uint32_t f2tf(float f) {
    uint32_t u;
    asm("cvt.rna.tf32.f32 %0, %1;" : "=r"(u) : "f"(f));
    return u;
}

// tanh(z) = 1 - 2/(exp(2z)+1); MUFU EX2 + fast div, ~1e-6 accurate, correct at +-inf.
__device__ __forceinline__ float tanh_fast(float z) {
    float e = __expf(2.0f * z);
    return 1.0f - __fdividef(2.0f, e + 1.0f);
}

__global__ __launch_bounds__(256, 2)
void node_step(const float* __restrict__ Xin,
               const float* __restrict__ W,
               const float* __restrict__ bias,
               const float* __restrict__ gamma,
               float* __restrict__ Xout)
{
    __shared__ uint32_t As[BM][BK + PAD];   // 128 x 36 words = 18 KB
    __shared__ uint32_t Bs[BN][BK + PAD];   //  64 x 36 words =  9 KB

    const int tid  = threadIdx.x;
    const int m0   = blockIdx.y * BM;
    const int n0   = blockIdx.x * BN;
    const int warp = tid >> 5;
    const int lane = tid & 31;
    const int g    = lane >> 2;   // group id (0..7)
    const int tg   = lane & 3;    // thread-in-group (0..3)
    const int wm   = warp & 3;    // warp row (0..3) -> 4*32 = 128 M
    const int wn   = warp >> 2;   // warp col (0..1) -> 2*32 =  64 N

    float acc[2][4][4];
    #pragma unroll
    for (int i = 0; i < 2; i++)
        #pragma unroll
        for (int j = 0; j < 4; j++)
            #pragma unroll
            for (int c = 0; c < 4; c++) acc[i][j][c] = 0.0f;

    for (int kt = 0; kt < Ktot; kt += BK) {
        // ---- load A tile: 128x32 floats (256 thr * 4 * float4), tf32-round ----
        #pragma unroll
        for (int i = 0; i < 4; i++) {
            int idx = tid + i * 256;      // float4 index within tile
            int row = idx >> 3;           // 8 float4 per row
            int c4  = (idx & 7) << 2;
            float4 v = *reinterpret_cast<const float4*>(
                Xin + (size_t)(m0 + row) * Ktot + kt + c4);
            As[row][c4 + 0] = f2tf(v.x);
            As[row][c4 + 1] = f2tf(v.y);
            As[row][c4 + 2] = f2tf(v.z);
            As[row][c4 + 3] = f2tf(v.w);
        }
        // ---- load B tile: 64x32 floats (W rows n0..n0+63) ----
        #pragma unroll
        for (int i = 0; i < 2; i++) {
            int idx = tid + i * 256;
            int row = idx >> 3;
            int c4  = (idx & 7) << 2;
            float4 v = *reinterpret_cast<const float4*>(
                W + (size_t)(n0 + row) * Ktot + kt + c4);
            Bs[row][c4 + 0] = f2tf(v.x);
            Bs[row][c4 + 1] = f2tf(v.y);
            Bs[row][c4 + 2] = f2tf(v.z);
            Bs[row][c4 + 3] = f2tf(v.w);
        }
        __syncthreads();

        #pragma unroll
        for (int ks = 0; ks < BK; ks += 8) {
            uint32_t af[2][4], bf[4][2];
            #pragma unroll
            for (int mt = 0; mt < 2; mt++) {
                int r = wm * 32 + mt * 16;
                af[mt][0] = As[r + g    ][ks + tg    ];
                af[mt][1] = As[r + g + 8][ks + tg    ];
                af[mt][2] = As[r + g    ][ks + tg + 4];
                af[mt][3] = As[r + g + 8][ks + tg + 4];
            }
            #pragma unroll
            for (int nt = 0; nt < 4; nt++) {
                int r = wn * 32 + nt * 8;
                bf[nt][0] = Bs[r + g][ks + tg    ];
                bf[nt][1] = Bs[r + g][ks + tg + 4];
            }
            #pragma unroll
            for (int mt = 0; mt < 2; mt++)
                #pragma unroll
                for (int nt = 0; nt < 4; nt++)
                    asm volatile(
                        "mma.sync.aligned.m16n8k8.row.col.f32.tf32.tf32.f32 "
                        "{%0,%1,%2,%3}, {%4,%5,%6,%7}, {%8,%9}, {%0,%1,%2,%3};"
                        : "+f"(acc[mt][nt][0]), "+f"(acc[mt][nt][1]),
                          "+f"(acc[mt][nt][2]), "+f"(acc[mt][nt][3])
                        : "r"(af[mt][0]), "r"(af[mt][1]),
                          "r"(af[mt][2]), "r"(af[mt][3]),
                          "r"(bf[nt][0]), "r"(bf[nt][1]));
        }
        __syncthreads();
    }

    // ---- fused epilogue: out = x + DT*(x*gamma + tanh(C + b)) ----
    #pragma unroll
    for (int mt = 0; mt < 2; mt++) {
        #pragma unroll
        for (int h = 0; h < 2; h++) {
            int m = m0 + wm * 32 + mt * 16 + g + h * 8;
            const float* xrow = Xin  + (size_t)m * Ntot;
            float*       orow = Xout + (size_t)m * Ntot;
            #pragma unroll
            for (int nt = 0; nt < 4; nt++) {
                int n = n0 + wn * 32 + nt * 8 + tg * 2;
                float2 xv = *reinterpret_cast<const float2*>(xrow + n);
                float2 bv = *reinterpret_cast<const float2*>(bias + n);
                float2 gv = *reinterpret_cast<const float2*>(gamma + n);
                float c0 = acc[mt][nt][h * 2 + 0];
                float c1 = acc[mt][nt][h * 2 + 1];
                float t0 = tanh_fast(c0 + bv.x);
                float t1 = tanh_fast(c1 + bv.y);
                float2 ov;
                ov.x = fmaf(DTF, fmaf(xv.x, gv.x, t0), xv.x);
                ov.y = fmaf(DTF, fmaf(xv.y, gv.y, t1), xv.y);
                *reinterpret_cast<float2*>(orow + n) = ov;
            }
        }
    }
}

extern "C" void kernel_launch(void* const* d_in, const int* in_sizes, int n_in,
                              void* d_out, int out_size)
{
    const float* x     = (const float*)d_in[0];  // (32768, 512)
    const float* W     = (const float*)d_in[1];  // (512, 512)
    const float* b     = (const float*)d_in[2];  // (512,)
    const float* gamma = (const float*)d_in[3];  // (512,)
    float* out = (float*)d_out;

    float* bufA = nullptr;
    float* bufB = nullptr;
    cudaGetSymbolAddress((void**)&bufA, g_bufA);
    cudaGetSymbolAddress((void**)&bufB, g_bufB);

    dim3 grid(Ntot / BN, Mtot / BM);   // (8, 256)
    dim3 block(256);

    for (int i = 0; i < NSTEPS; i++) {
        const float* src = (i == 0) ? x : ((i & 1) ? bufA : bufB);
        float* dst = (i == NSTEPS - 1) ? out : ((i & 1) ? bufB : bufA);
        node_step<<<grid, block>>>(src, W, b, gamma, dst);
    }
}

// round 3
// speedup vs baseline: 1.4115x; 1.4115x over previous
#include <cuda_runtime.h>
#include <cstdint>

// nODE: 50 Euler steps x <- x + DT*(x*gamma + tanh(x @ W^T + b)), M=32768, N=K=512.
// Legacy mma.sync.m16n8k8.tf32 (tcgen05 unavailable: harness PTX target is compute_103).
// CTA tile 256x64, warp tile 64x32 (8 warps, 4x2), BK=32, cp.async double buffer,
// k-permuted fragments -> all LDS.64, padded smem rows (160B) -> conflict-free.

constexpr int Mtot = 32768;
constexpr int Ntot = 512;
constexpr int Ktot = 512;
constexpr int BM = 256;
constexpr int BN = 64;
constexpr int BK = 32;
constexpr int NKT = Ktot / BK;          // 16
constexpr int ROWW = 40;                // words per smem row: 32 data + 8 pad (160B)
constexpr int A_WORDS = BM * ROWW;      // 10240
constexpr int B_WORDS = BN * ROWW;      // 2560
constexpr int STAGE_WORDS = A_WORDS + B_WORDS;       // 12800
constexpr int SMEM_BYTES = 2 * STAGE_WORDS * 4;      // 102400
constexpr int NSTEPS = 50;
constexpr float DTF = 1.0f / 50.0f;

// ping-pong scratch (allocation-free rule: __device__ globals)
__device__ float g_bufA[(size_t)Mtot * Ntot];
__device__ float g_bufB[(size_t)Mtot * Ntot];

__device__ __forceinline__ uint32_t smem_u32(const void* p) {
    uint32_t a;
    asm("{ .reg .u64 t; cvta.to.shared.u64 t, %1; cvt.u32.u64 %0, t; }" : "=r"(a) : "l"(p));
    return a;
}
__device__ __forceinline__ void cp_async16(uint32_t dst, const void* src) {
    asm volatile("cp.async.cg.shared.global [%0], [%1], 16;" :: "r"(dst), "l"(src) : "memory");
}
// tanh(z) = 1 - 2/(exp(2z)+1): MUFU EX2 + fast div, ~1e-6 accurate, correct at +-inf
__device__ __forceinline__ float tanh_fast(float z) {
    float e = __expf(2.0f * z);
    return 1.0f - __fdividef(2.0f, e + 1.0f);
}

__global__ __launch_bounds__(256, 2)
void node_step(const float* __restrict__ Xin, const float* __restrict__ W,
               const float* __restrict__ bias, const float* __restrict__ gamma,
               float* __restrict__ Xout)
{
    extern __shared__ __align__(16) float smem[];
    const uint32_t sbase = smem_u32(smem);

    const int tid  = threadIdx.x;
    const int wid  = tid >> 5;
    const int lane = tid & 31;
    const int g    = lane >> 2;          // 0..7 (fragment row group)
    const int tg   = lane & 3;           // 0..3 (fragment k group)
    const int wm   = wid >> 1;           // 0..3: warp row -> 64 M rows each
    const int wn   = wid & 1;            // 0..1: warp col -> 32 N cols each
    const int m0   = blockIdx.y * BM;
    const int n0   = blockIdx.x * BN;

    float acc[4][4][4];
    #pragma unroll
    for (int mt = 0; mt < 4; mt++)
        #pragma unroll
        for (int nt = 0; nt < 4; nt++)
            #pragma unroll
            for (int c = 0; c < 4; c++) acc[mt][nt][c] = 0.0f;

    // ---- async tile loader: A 256x32, B 64x32 (row-major, 160B smem rows) ----
    auto issue_loads = [&](int kt, int s) {
        const uint32_t a_s = sbase + (uint32_t)(s * STAGE_WORDS) * 4;
        const uint32_t b_s = a_s + (uint32_t)A_WORDS * 4;
        const float* gA = Xin + (size_t)m0 * Ktot + kt * BK;
        #pragma unroll
        for (int i = 0; i < 8; i++) {                 // 2048 16B chunks
            int idx = tid + i * 256;
            int r = idx >> 3, c = idx & 7;
            cp_async16(a_s + (uint32_t)(r * ROWW + c * 4) * 4,
                       gA + (size_t)r * Ktot + c * 4);
        }
        const float* gB = W + (size_t)n0 * Ktot + kt * BK;
        #pragma unroll
        for (int i = 0; i < 2; i++) {                 // 512 16B chunks
            int idx = tid + i * 256;
            int r = idx >> 3, c = idx & 7;
            cp_async16(b_s + (uint32_t)(r * ROWW + c * 4) * 4,
                       gB + (size_t)r * Ktot + c * 4);
        }
        asm volatile("cp.async.commit_group;" ::: "memory");
    };

    issue_loads(0, 0);

    for (int kt = 0; kt < NKT; kt++) {
        const int s = kt & 1;
        if (kt + 1 < NKT) {
            issue_loads(kt + 1, s ^ 1);
            asm volatile("cp.async.wait_group 1;" ::: "memory");
        } else {
            asm volatile("cp.async.wait_group 0;" ::: "memory");
        }
        __syncthreads();

        const float* As = smem + s * STAGE_WORDS;
        const float* Bs = As + A_WORDS;
        const float* a_base = As + (wm * 64 + g) * ROWW + 2 * tg;
        const float* b_base = Bs + (wn * 32 + g) * ROWW + 2 * tg;

        #pragma unroll
        for (int ch = 0; ch < 4; ch++) {             // k chunks of 8
            // k-permutation: MMA k-slot tg <- orig col 2tg, slot tg+4 <- 2tg+1.
            // Valid because A and B use the same permutation of the k axis.
            uint32_t af[4][4];
            #pragma unroll
            for (int mt = 0; mt < 4; mt++) {
                const float* p = a_base + mt * 16 * ROWW + ch * 8;
                float2 p1 = *reinterpret_cast<const float2*>(p);
                float2 p2 = *reinterpret_cast<const float2*>(p + 8 * ROWW);
                af[mt][0] = __float_as_uint(p1.x);   // (g,    k=tg)
                af[mt][1] = __float_as_uint(p2.x);   // (g+8,  k=tg)
                af[mt][2] = __float_as_uint(p1.y);   // (g,    k=tg+4)
                af[mt][3] = __float_as_uint(p2.y);   // (g+8,  k=tg+4)
            }
            uint32_t bf[4][2];
            #pragma unroll
            for (int nt = 0; nt < 4; nt++) {
                float2 q = *reinterpret_cast<const float2*>(b_base + nt * 8 * ROWW + ch * 8);
                bf[nt][0] = __float_as_uint(q.x);
                bf[nt][1] = __float_as_uint(q.y);
            }
            #pragma unroll
            for (int mt = 0; mt < 4; mt++)
                #pragma unroll
                for (int nt = 0; nt < 4; nt++)
                    asm volatile(
                        "mma.sync.aligned.m16n8k8.row.col.f32.tf32.tf32.f32 "
                        "{%0,%1,%2,%3}, {%4,%5,%6,%7}, {%8,%9}, {%0,%1,%2,%3};"
                        : "+f"(acc[mt][nt][0]), "+f"(acc[mt][nt][1]),
                          "+f"(acc[mt][nt][2]), "+f"(acc[mt][nt][3])
                        : "r"(af[mt][0]), "r"(af[mt][1]),
                          "r"(af[mt][2]), "r"(af[mt][3]),
                          "r"(bf[nt][0]), "r"(bf[nt][1]));
        }
        __syncthreads();
    }

    // ---- fused epilogue: out = x + DT*(x*gamma + tanh(C + b)) ----
    // D frag: d0,d1 at (row g,   cols 2tg,2tg+1); d2,d3 at (row g+8, same cols)
    float2 bv[4], gv[4];
    #pragma unroll
    for (int nt = 0; nt < 4; nt++) {
        int n = n0 + wn * 32 + nt * 8 + 2 * tg;
        bv[nt] = *reinterpret_cast<const float2*>(bias + n);
        gv[nt] = *reinterpret_cast<const float2*>(gamma + n);
    }
    #pragma unroll
    for (int mt = 0; mt < 4; mt++) {
        #pragma unroll
        for (int h = 0; h < 2; h++) {
            int m = m0 + wm * 64 + mt * 16 + g + h * 8;
            const float* xrow = Xin  + (size_t)m * Ntot;
            float*       orow = Xout + (size_t)m * Ntot;
            #pragma unroll
            for (int nt = 0; nt < 4; nt++) {
                int n = n0 + wn * 32 + nt * 8 + 2 * tg;
                float2 xv = *reinterpret_cast<const float2*>(xrow + n);
                float c0 = acc[mt][nt][h * 2 + 0];
                float c1 = acc[mt][nt][h * 2 + 1];
                float2 ov;
                ov.x = fmaf(DTF, fmaf(xv.x, gv[nt].x, tanh_fast(c0 + bv[nt].x)), xv.x);
                ov.y = fmaf(DTF, fmaf(xv.y, gv[nt].y, tanh_fast(c1 + bv[nt].y)), xv.y);
                *reinterpret_cast<float2*>(orow + n) = ov;
            }
        }
    }
}

extern "C" void kernel_launch(void* const* d_in, const int* in_sizes, int n_in,
                              void* d_out, int out_size)
{
    const float* x     = (const float*)d_in[0];
    const float* W     = (const float*)d_in[1];
    const float* b     = (const float*)d_in[2];
    const float* gamma = (const float*)d_in[3];
    float* out = (float*)d_out;

    float* bufA = nullptr;
    float* bufB = nullptr;
    cudaGetSymbolAddress((void**)&bufA, g_bufA);
    cudaGetSymbolAddress((void**)&bufB, g_bufB);

    cudaFuncSetAttribute(node_step, cudaFuncAttributeMaxDynamicSharedMemorySize, SMEM_BYTES);

    dim3 grid(Ntot / BN, Mtot / BM);   // (8, 128)
    dim3 block(256);

    for (int i = 0; i < NSTEPS; i++) {
        const float* src = (i == 0) ? x : ((i & 1) ? bufA : bufB);
        float* dst = (i == NSTEPS - 1) ? out : ((i & 1) ? bufB : bufA);
        node_step<<<grid, block, SMEM_BYTES>>>(src, W, b, gamma, dst);
    }
}